// round 1
// baseline (speedup 1.0000x reference)
#include <cuda_runtime.h>
#include <cuda_bf16.h>
#include <math.h>

// ---------------------------------------------------------------------------
// T2T-ViT forward: B=64, N=197 (196+cls), C=768, D=12 layers, H=12, dk=64,
// F=3072, V=1000.  Full fp32 baseline.
// ---------------------------------------------------------------------------

#define BB   64
#define NN   197
#define CC   768
#define TT   (BB * NN)        // 12608
#define HH   12
#define DK   64
#define FF   3072
#define NL   12
#define VV   1000

// --------------------------- scratch (static device) -----------------------
__device__ float g_h  [TT * CC];      // residual stream
__device__ float g_y  [TT * CC];      // layernorm output
__device__ float g_qkv[TT * 3 * CC];  // qkv projections
__device__ float g_o  [TT * CC];      // attention output
__device__ float g_m  [TT * FF];      // mlp hidden
__device__ float g_cls[BB * CC];      // normalized cls tokens

// --------------------------- embed: cls + x + sinusoidal PE ----------------
__global__ void embed_kernel(const float* __restrict__ x,
                             const float* __restrict__ cls,
                             float* __restrict__ h)
{
    int row = blockIdx.x;            // b*197 + n
    int b = row / NN, n = row % NN;
    for (int c = threadIdx.x; c < CC; c += blockDim.x) {
        float base = (n == 0) ? cls[c]
                              : x[((size_t)b * (NN - 1) + (n - 1)) * CC + c];
        int jj = c & ~1;
        float div = __expf(-9.210340371976184f * (float)jj / 768.0f);
        float ang = (float)n * div;
        float pe  = (c & 1) ? cosf(ang) : sinf(ang);
        h[(size_t)row * CC + c] = base + pe;
    }
}

// --------------------------- layernorm (one block per row) -----------------
// input row = blockIdx.x * in_row_stride ; output row = blockIdx.x
__global__ void ln_kernel(const float* __restrict__ x,
                          const float* __restrict__ w,
                          const float* __restrict__ bns,
                          float* __restrict__ y,
                          int in_row_stride)
{
    const float* xr = x + (size_t)blockIdx.x * in_row_stride * CC;
    float* yr = y + (size_t)blockIdx.x * CC;
    int t = threadIdx.x;                  // 256 threads, 3 elems each
    float v0 = xr[t], v1 = xr[t + 256], v2 = xr[t + 512];
    float s = v0 + v1 + v2;
    float q = v0 * v0 + v1 * v1 + v2 * v2;
    #pragma unroll
    for (int o = 16; o; o >>= 1) {
        s += __shfl_xor_sync(0xffffffffu, s, o);
        q += __shfl_xor_sync(0xffffffffu, q, o);
    }
    __shared__ float ss[8], qs[8];
    if ((t & 31) == 0) { ss[t >> 5] = s; qs[t >> 5] = q; }
    __syncthreads();
    float tot = 0.f, totq = 0.f;
    #pragma unroll
    for (int i = 0; i < 8; i++) { tot += ss[i]; totq += qs[i]; }
    float mu   = tot * (1.0f / 768.0f);
    float var  = totq * (1.0f / 768.0f) - mu * mu;
    float rstd = rsqrtf(var + 1e-5f);
    yr[t]       = (v0 - mu) * rstd * w[t]       + bns[t];
    yr[t + 256] = (v1 - mu) * rstd * w[t + 256] + bns[t + 256];
    yr[t + 512] = (v2 - mu) * rstd * w[t + 512] + bns[t + 512];
}

// --------------------------- GEMM: out = A[M,K] * W[Nd,K]^T (+epilogue) ----
// 128x128 tile, BK=8, 256 threads, 8x8 per thread.
template<bool BIAS, bool GELU, bool RES>
__global__ void gemm_nt(const float* __restrict__ A,
                        const float* __restrict__ W,
                        const float* __restrict__ bias,
                        const float* __restrict__ res,
                        float* __restrict__ out,
                        int M, int Nd, int K)
{
    const int BM = 128, BN = 128, BK = 8;
    __shared__ float As[BK][BM + 4];
    __shared__ float Ws[BK][BN + 4];

    int t  = threadIdx.x;
    int tx = t & 15, ty = t >> 4;
    int m0 = blockIdx.x * BM, n0 = blockIdx.y * BN;

    int lrow = t >> 1;            // 0..127
    int lk   = (t & 1) * 4;       // 0 or 4

    float acc[8][8];
    #pragma unroll
    for (int i = 0; i < 8; i++)
        #pragma unroll
        for (int j = 0; j < 8; j++) acc[i][j] = 0.f;

    for (int k0 = 0; k0 < K; k0 += BK) {
        int gm = m0 + lrow;
        float4 va = (gm < M) ? *(const float4*)(A + (size_t)gm * K + k0 + lk)
                             : make_float4(0.f, 0.f, 0.f, 0.f);
        As[lk + 0][lrow] = va.x; As[lk + 1][lrow] = va.y;
        As[lk + 2][lrow] = va.z; As[lk + 3][lrow] = va.w;

        int gn = n0 + lrow;
        float4 vw = (gn < Nd) ? *(const float4*)(W + (size_t)gn * K + k0 + lk)
                              : make_float4(0.f, 0.f, 0.f, 0.f);
        Ws[lk + 0][lrow] = vw.x; Ws[lk + 1][lrow] = vw.y;
        Ws[lk + 2][lrow] = vw.z; Ws[lk + 3][lrow] = vw.w;

        __syncthreads();
        #pragma unroll
        for (int k = 0; k < BK; k++) {
            float ra[8], rb[8];
            *(float4*)(ra)     = *(const float4*)&As[k][ty * 8];
            *(float4*)(ra + 4) = *(const float4*)&As[k][ty * 8 + 4];
            *(float4*)(rb)     = *(const float4*)&Ws[k][tx * 8];
            *(float4*)(rb + 4) = *(const float4*)&Ws[k][tx * 8 + 4];
            #pragma unroll
            for (int i = 0; i < 8; i++)
                #pragma unroll
                for (int j = 0; j < 8; j++)
                    acc[i][j] += ra[i] * rb[j];
        }
        __syncthreads();
    }

    #pragma unroll
    for (int i = 0; i < 8; i++) {
        int gm = m0 + ty * 8 + i;
        if (gm >= M) continue;
        #pragma unroll
        for (int j = 0; j < 8; j++) {
            int gn = n0 + tx * 8 + j;
            if (gn >= Nd) continue;
            float v = acc[i][j];
            if (BIAS) v += bias[gn];
            if (GELU) v = 0.5f * v * (1.0f + erff(v * 0.70710678118654752f));
            if (RES)  v += res[(size_t)gm * Nd + gn];
            out[(size_t)gm * Nd + gn] = v;
        }
    }
}

// --------------------------- fused attention per (b,h) ---------------------
// K,V tiles live in smem; one thread per query row; two-pass softmax.
__global__ void attn_kernel(const float* __restrict__ qkv,
                            float* __restrict__ o)
{
    extern __shared__ float smem[];
    float* Ks = smem;                 // NN*DK
    float* Vs = smem + NN * DK;       // NN*DK
    int bh = blockIdx.x;
    int b = bh / HH, h = bh % HH;
    const float* base = qkv + (size_t)b * NN * (3 * CC);

    for (int idx = threadIdx.x; idx < NN * DK; idx += blockDim.x) {
        int n = idx >> 6, d = idx & 63;
        Ks[idx] = base[(size_t)n * (3 * CC) +     CC + h * DK + d];
        Vs[idx] = base[(size_t)n * (3 * CC) + 2 * CC + h * DK + d];
    }
    __syncthreads();

    int i = threadIdx.x;
    if (i < NN) {
        float q[DK];
        const float* qp = base + (size_t)i * (3 * CC) + h * DK;
        #pragma unroll
        for (int d = 0; d < DK; d += 4) {
            float4 v = *(const float4*)(qp + d);
            q[d] = v.x * 0.125f; q[d + 1] = v.y * 0.125f;
            q[d + 2] = v.z * 0.125f; q[d + 3] = v.w * 0.125f;
        }
        // pass 1: row max
        float mx = -1e30f;
        for (int j = 0; j < NN; j++) {
            const float* kr = Ks + j * DK;
            float s = 0.f;
            #pragma unroll
            for (int d = 0; d < DK; d++) s += q[d] * kr[d];
            mx = fmaxf(mx, s);
        }
        // pass 2: exp-sum + weighted V accumulate
        float l = 0.f;
        float accv[DK];
        #pragma unroll
        for (int d = 0; d < DK; d++) accv[d] = 0.f;
        for (int j = 0; j < NN; j++) {
            const float* kr = Ks + j * DK;
            float s = 0.f;
            #pragma unroll
            for (int d = 0; d < DK; d++) s += q[d] * kr[d];
            float p = __expf(s - mx);
            l += p;
            const float* vr = Vs + j * DK;
            #pragma unroll
            for (int d = 0; d < DK; d++) accv[d] += p * vr[d];
        }
        float inv = 1.0f / l;
        float* op = o + (size_t)(b * NN + i) * CC + h * DK;
        #pragma unroll
        for (int d = 0; d < DK; d++) op[d] = accv[d] * inv;
    }
}

// ---------------------------------------------------------------------------
extern "C" void kernel_launch(void* const* d_in, const int* in_sizes, int n_in,
                              void* d_out, int out_size)
{
    const float* x      = (const float*)d_in[0];
    const float* cls    = (const float*)d_in[1];
    const float* qkv_w  = (const float*)d_in[2];
    const float* proj_w = (const float*)d_in[3];
    const float* proj_b = (const float*)d_in[4];
    const float* ln1_w  = (const float*)d_in[5];
    const float* ln1_b  = (const float*)d_in[6];
    const float* ln2_w  = (const float*)d_in[7];
    const float* ln2_b  = (const float*)d_in[8];
    const float* fc1_w  = (const float*)d_in[9];
    const float* fc1_b  = (const float*)d_in[10];
    const float* fc2_w  = (const float*)d_in[11];
    const float* fc2_b  = (const float*)d_in[12];
    const float* norm_w = (const float*)d_in[13];
    const float* norm_b = (const float*)d_in[14];
    const float* head_w = (const float*)d_in[15];
    const float* head_b = (const float*)d_in[16];
    float* out = (float*)d_out;

    float *ph, *py, *pqkv, *po, *pm, *pcls;
    cudaGetSymbolAddress((void**)&ph,   g_h);
    cudaGetSymbolAddress((void**)&py,   g_y);
    cudaGetSymbolAddress((void**)&pqkv, g_qkv);
    cudaGetSymbolAddress((void**)&po,   g_o);
    cudaGetSymbolAddress((void**)&pm,   g_m);
    cudaGetSymbolAddress((void**)&pcls, g_cls);

    const int attn_smem = NN * DK * 2 * (int)sizeof(float);   // 100,864 B
    cudaFuncSetAttribute(attn_kernel,
                         cudaFuncAttributeMaxDynamicSharedMemorySize, attn_smem);

    // embed
    embed_kernel<<<TT, 256>>>(x, cls, ph);

    const int MT = (TT + 127) / 128;  // 99 row tiles

    for (int d = 0; d < NL; d++) {
        const float* qw  = qkv_w  + (size_t)d * 3 * CC * CC;
        const float* pw  = proj_w + (size_t)d * CC * CC;
        const float* pb  = proj_b + (size_t)d * CC;
        const float* l1w = ln1_w  + (size_t)d * CC;
        const float* l1b = ln1_b  + (size_t)d * CC;
        const float* l2w = ln2_w  + (size_t)d * CC;
        const float* l2b = ln2_b  + (size_t)d * CC;
        const float* f1w = fc1_w  + (size_t)d * FF * CC;
        const float* f1b = fc1_b  + (size_t)d * FF;
        const float* f2w = fc2_w  + (size_t)d * CC * FF;
        const float* f2b = fc2_b  + (size_t)d * CC;

        // y = LN1(h)
        ln_kernel<<<TT, 256>>>(ph, l1w, l1b, py, 1);
        // qkv = y @ qw^T
        gemm_nt<false, false, false><<<dim3(MT, (3 * CC) / 128), 256>>>(
            py, qw, nullptr, nullptr, pqkv, TT, 3 * CC, CC);
        // o = attention(qkv)
        attn_kernel<<<BB * HH, 256, attn_smem>>>(pqkv, po);
        // h = h + o @ pw^T + pb
        gemm_nt<true, false, true><<<dim3(MT, CC / 128), 256>>>(
            po, pw, pb, ph, ph, TT, CC, CC);
        // y = LN2(h)
        ln_kernel<<<TT, 256>>>(ph, l2w, l2b, py, 1);
        // m = gelu(y @ f1w^T + f1b)
        gemm_nt<true, true, false><<<dim3(MT, FF / 128), 256>>>(
            py, f1w, f1b, nullptr, pm, TT, FF, CC);
        // h = h + m @ f2w^T + f2b
        gemm_nt<true, false, true><<<dim3(MT, CC / 128), 256>>>(
            pm, f2w, f2b, ph, ph, TT, CC, FF);
    }

    // final LN on cls rows only -> g_cls [64, 768]
    ln_kernel<<<BB, 256>>>(ph, norm_w, norm_b, pcls, NN);

    // out = cls @ head_w^T + head_b   [64, 1000]
    gemm_nt<true, false, false><<<dim3(1, (VV + 127) / 128), 256>>>(
        pcls, head_w, head_b, nullptr, out, BB, VV, CC);
}

// round 3
// speedup vs baseline: 2.1708x; 2.1708x over previous
#include <cuda_runtime.h>
#include <cuda_bf16.h>
#include <math.h>
#include <stdint.h>

// ---------------------------------------------------------------------------
// T2T-ViT forward. B=64, N=197, C=768, D=12, H=12, dk=64, F=3072, V=1000.
// GEMMs: bf16-split (3 MMA) tensor cores.
//   - sm_103a pass (if any): tcgen05 (guarded by __CUDA_ARCH_FEAT_SM103_ALL)
//   - otherwise: mma.sync.m16n8k16 bf16 HMMA (legal on plain sm_103)
// ---------------------------------------------------------------------------

#define BB   64
#define NN   197
#define CC   768
#define TT   (BB * NN)        // 12608
#define MP   12672            // padded to 99*128
#define HH   12
#define DK   64
#define FF   3072
#define NL   12
#define VV   1000

#define GT_SMEM (1024 + 65536)

// --------------------------- scratch (static device, zero-init) -------------
__device__ float g_h  [MP * CC];
__device__ float g_y  [MP * CC];
__device__ float g_qkv[MP * 3 * CC];
__device__ float g_o  [MP * CC];
__device__ float g_m  [MP * FF];
__device__ float g_cls[BB * CC];

// --------------------------- helpers ----------------------------------------
__device__ __forceinline__ uint32_t smem_u32(const void* p) {
    uint32_t a;
    asm("{ .reg .u64 t; cvta.to.shared.u64 t, %1; cvt.u32.u64 %0, t; }"
        : "=r"(a) : "l"(p));
    return a;
}

// pack two floats as bf16x2 (lo = a, hi = b), single instruction
__device__ __forceinline__ uint32_t cvt_bf16x2(float a, float b) {
    uint32_t r;
    asm("cvt.rn.bf16x2.f32 %0, %2, %1;" : "=r"(r) : "f"(a), "f"(b));
    return r;
}
// hi/lo split of a float4 into packed bf16x2 words
__device__ __forceinline__ void split4(float4 v, uint32_t& h01, uint32_t& h23,
                                       uint32_t& l01, uint32_t& l23) {
    h01 = cvt_bf16x2(v.x, v.y);
    h23 = cvt_bf16x2(v.z, v.w);
    float hx = __uint_as_float(h01 << 16);
    float hy = __uint_as_float(h01 & 0xffff0000u);
    float hz = __uint_as_float(h23 << 16);
    float hw = __uint_as_float(h23 & 0xffff0000u);
    l01 = cvt_bf16x2(v.x - hx, v.y - hy);
    l23 = cvt_bf16x2(v.z - hz, v.w - hw);
}

__device__ __forceinline__ float gelu_exact(float f) {
    return 0.5f * f * (1.0f + erff(f * 0.70710678118654752f));
}

#if defined(__CUDA_ARCH__) && defined(__CUDA_ARCH_FEAT_SM103_ALL)
// ======================= tcgen05 path helpers ================================
__device__ __forceinline__ uint32_t elect_one() {
    uint32_t pred;
    asm volatile("{\n\t.reg .pred p;\n\telect.sync _|p, 0xFFFFFFFF;\n\t"
                 "selp.b32 %0, 1, 0, p;\n\t}" : "=r"(pred));
    return pred;
}
#define MBAR_INIT(addr, cnt) \
    asm volatile("mbarrier.init.shared.b64 [%0], %1;" :: "r"(addr), "r"(cnt) : "memory")
#define MBAR_WAIT(addr, parity) do {                                          \
    uint32_t _m = (addr); uint32_t _p = (parity); uint32_t _d;                \
    asm volatile("{\n\t.reg .pred p;\n\t"                                     \
        "mbarrier.try_wait.parity.acquire.cta.shared::cta.b64 p, [%1], %2;\n\t" \
        "selp.b32 %0, 1, 0, p;\n\t}" : "=r"(_d) : "r"(_m), "r"(_p) : "memory"); \
    if (!_d) {                                                                \
        asm volatile("{\n\t.reg .pred P1;\n\tWL_%=:\n\t"                      \
            "mbarrier.try_wait.parity.acquire.cta.shared::cta.b64 P1, [%0], %1, 0x989680;\n\t" \
            "@P1 bra.uni WD_%=;\n\tbra.uni WL_%=;\n\tWD_%=:\n\t}"             \
            :: "r"(_m), "r"(_p) : "memory");                                  \
    }                                                                         \
} while (0)
#define TC_ALLOC(smem_addr, ncols) \
    asm volatile("tcgen05.alloc.cta_group::1.sync.aligned.shared::cta.b32 [%0], %1;" \
                 :: "r"(smem_addr), "r"(ncols) : "memory")
#define TC_DEALLOC(tmem, ncols) \
    asm volatile("tcgen05.dealloc.cta_group::1.sync.aligned.b32 %0, %1;" \
                 :: "r"(tmem), "r"(ncols))
#define TC_COMMIT(mbar) \
    asm volatile("tcgen05.commit.cta_group::1.mbarrier::arrive::one.shared::cluster.b64 [%0];" \
                 :: "r"(mbar) : "memory")
#define TC_FENCE_AFTER()  asm volatile("tcgen05.fence::after_thread_sync;" ::: "memory")
#define TC_FENCE_BEFORE() asm volatile("tcgen05.fence::before_thread_sync;" ::: "memory")
#define TC_WAIT_LD()      asm volatile("tcgen05.wait::ld.sync.aligned;" ::: "memory")
#define FENCE_ASYNC_SHARED() asm volatile("fence.proxy.async.shared::cta;" ::: "memory")

#define TC_LD_X32(r, tmem_addr)                                               \
    asm volatile(                                                             \
        "tcgen05.ld.sync.aligned.32x32b.x32.b32 "                             \
        "{%0, %1, %2, %3, %4, %5, %6, %7, "                                   \
        " %8, %9, %10, %11, %12, %13, %14, %15, "                             \
        " %16, %17, %18, %19, %20, %21, %22, %23, "                           \
        " %24, %25, %26, %27, %28, %29, %30, %31}, [%32];"                    \
        : "=r"((r)[0]),  "=r"((r)[1]),  "=r"((r)[2]),  "=r"((r)[3]),          \
          "=r"((r)[4]),  "=r"((r)[5]),  "=r"((r)[6]),  "=r"((r)[7]),          \
          "=r"((r)[8]),  "=r"((r)[9]),  "=r"((r)[10]), "=r"((r)[11]),         \
          "=r"((r)[12]), "=r"((r)[13]), "=r"((r)[14]), "=r"((r)[15]),         \
          "=r"((r)[16]), "=r"((r)[17]), "=r"((r)[18]), "=r"((r)[19]),         \
          "=r"((r)[20]), "=r"((r)[21]), "=r"((r)[22]), "=r"((r)[23]),         \
          "=r"((r)[24]), "=r"((r)[25]), "=r"((r)[26]), "=r"((r)[27]),         \
          "=r"((r)[28]), "=r"((r)[29]), "=r"((r)[30]), "=r"((r)[31])          \
        : "r"(tmem_addr))

__device__ __forceinline__ void mma_bf16_ss(uint32_t d, uint64_t ad, uint64_t bd,
                                            uint32_t idesc, uint32_t en) {
    asm volatile(
        "{\n\t.reg .pred p;\n\t"
        "setp.ne.u32 p, %4, 0;\n\t"
        "tcgen05.mma.cta_group::1.kind::f16 [%0], %1, %2, %3, {%5, %5, %5, %5}, p;\n\t"
        "}"
        :: "r"(d), "l"(ad), "l"(bd), "r"(idesc), "r"(en), "r"(0u)
        : "memory");
}
__device__ __forceinline__ uint64_t make_desc_sw128(uint32_t addr) {
    const uint64_t base = (uint64_t(2) << 61) | (uint64_t(1) << 46)
                        | (uint64_t(64) << 32) | (uint64_t(1) << 16);
    return base | ((uint64_t)(addr >> 4) & 0x3FFF);
}
__device__ __forceinline__ uint32_t sw128(uint32_t off) {
    return off ^ ((off >> 3) & 0x70);
}
#else
// ======================= mma.sync fallback helper ============================
__device__ __forceinline__ void mma16816(float* d, const uint32_t* a,
                                         uint32_t b0, uint32_t b1) {
    asm volatile(
        "mma.sync.aligned.m16n8k16.row.col.f32.bf16.bf16.f32 "
        "{%0,%1,%2,%3}, {%4,%5,%6,%7}, {%8,%9}, {%0,%1,%2,%3};"
        : "+f"(d[0]), "+f"(d[1]), "+f"(d[2]), "+f"(d[3])
        : "r"(a[0]), "r"(a[1]), "r"(a[2]), "r"(a[3]), "r"(b0), "r"(b1));
}
#endif

// --------------------------- GEMM kernel ------------------------------------
// out[M,Nd] = A[M,K] @ W[Nd,K]^T (+bias/gelu/res). M%128==0, Nd%128==0, K%64==0.
// Block tile 128x128, 256 threads.
template<bool BIAS, bool GELU, bool RES>
__global__ __launch_bounds__(256, 2)
void gemm_tc(const float* __restrict__ A, const float* __restrict__ W,
             const float* __restrict__ bias, const float* __restrict__ res,
             float* __restrict__ out, int M, int Nd, int K)
{
    extern __shared__ char smem[];
    const int tid = threadIdx.x, wid = tid >> 5, lane = tid & 31;
    const int m0 = blockIdx.x * 128, n0 = blockIdx.y * 128;

#if defined(__CUDA_ARCH__) && defined(__CUDA_ARCH_FEAT_SM103_ALL)
    // ======================= tcgen05 path (conservative, single buffer) =====
    uint32_t sb = smem_u32(smem);
    if (wid == 0) TC_ALLOC(sb, 128);
    if (tid == 0) MBAR_INIT(sb + 8, 1);
    __syncthreads();
    uint32_t tmem;
    asm volatile("ld.shared.b32 %0, [%1];" : "=r"(tmem) : "r"(sb));

    const int NS = K / 64;
    const uint32_t idesc = (1u << 4) | (1u << 7) | (1u << 10)
                         | ((128u / 8) << 17) | ((128u / 16) << 24);
    const uint32_t AH = 1024, AL = 1024 + 16384, BH = 1024 + 32768, BL = 1024 + 49152;

    for (int s = 0; s < NS; s++) {
        int k0 = s * 64;
        __syncthreads();
        #pragma unroll
        for (int it = 0; it < 8; it++) {
            int idx = tid + it * 256;
            int row = idx >> 4, c4 = (idx & 15) << 2;
            uint32_t sw = sw128((uint32_t)(row * 128 + c4 * 2));
            {   // A tile 128x64
                float4 v = *(const float4*)(A + (size_t)(m0 + row) * K + k0 + c4);
                uint32_t h01, h23, l01, l23; split4(v, h01, h23, l01, l23);
                *(uint2*)(smem + AH + sw) = make_uint2(h01, h23);
                *(uint2*)(smem + AL + sw) = make_uint2(l01, l23);
            }
            {   // B tile 128x64
                float4 v = *(const float4*)(W + (size_t)(n0 + row) * K + k0 + c4);
                uint32_t h01, h23, l01, l23; split4(v, h01, h23, l01, l23);
                *(uint2*)(smem + BH + sw) = make_uint2(h01, h23);
                *(uint2*)(smem + BL + sw) = make_uint2(l01, l23);
            }
        }
        FENCE_ASYNC_SHARED();
        __syncthreads();

        if (wid == 0 && elect_one()) {
            uint64_t dAh = make_desc_sw128(sb + AH);
            uint64_t dAl = make_desc_sw128(sb + AL);
            uint64_t dBh = make_desc_sw128(sb + BH);
            uint64_t dBl = make_desc_sw128(sb + BL);
            #pragma unroll
            for (int kc = 0; kc < 4; kc++) {
                uint32_t en0 = (s == 0 && kc == 0) ? 0u : 1u;
                mma_bf16_ss(tmem, dAh + kc * 2, dBh + kc * 2, idesc, en0);
                mma_bf16_ss(tmem, dAh + kc * 2, dBl + kc * 2, idesc, 1u);
                mma_bf16_ss(tmem, dAl + kc * 2, dBh + kc * 2, idesc, 1u);
            }
            TC_COMMIT(sb + 8);
        }
        MBAR_WAIT(sb + 8, (uint32_t)(s & 1));
    }
    TC_FENCE_AFTER();

    // epilogue: 8 warps; subpartition = wid&3 -> rows, wid>>2 -> column half
    int rg = wid & 3, cg = wid >> 2;
    int gm = m0 + rg * 32 + lane;
    #pragma unroll
    for (int c = 0; c < 2; c++) {
        uint32_t col = (uint32_t)(cg * 64 + c * 32);
        uint32_t dreg[32];
        TC_LD_X32(dreg, tmem + col);
        TC_WAIT_LD();
        int gn0 = n0 + (int)col;
        #pragma unroll
        for (int k = 0; k < 32; k += 4) {
            float4 r4;
            if (RES) r4 = *(const float4*)(res + (size_t)gm * Nd + gn0 + k);
            float vv[4];
            #pragma unroll
            for (int e = 0; e < 4; e++) {
                float f = __uint_as_float(dreg[k + e]);
                if (BIAS) f += bias[gn0 + k + e];
                if (GELU) f = gelu_exact(f);
                if (RES)  f += (&r4.x)[e];
                vv[e] = f;
            }
            *(float4*)(out + (size_t)gm * Nd + gn0 + k) =
                make_float4(vv[0], vv[1], vv[2], vv[3]);
        }
    }
    TC_FENCE_BEFORE();
    __syncthreads();
    if (wid == 0) TC_DEALLOC(tmem, 128);

#else
    // ======================= mma.sync bf16-split fallback ====================
    // smem planes: bf16, padded row stride 40 elements (80B), conflict-free.
    const uint32_t AH = 0, ALo = 10240, BH = 20480, BLo = 30720;
    const int warp_m = wid & 1, warp_n = wid >> 1;   // 2 x 4 warps
    const int g = lane >> 2, t = lane & 3;

    float acc[4][4][4];
    #pragma unroll
    for (int i = 0; i < 4; i++)
        #pragma unroll
        for (int j = 0; j < 4; j++)
            #pragma unroll
            for (int e = 0; e < 4; e++) acc[i][j][e] = 0.f;

    const int NS = K / 32;
    for (int s = 0; s < NS; s++) {
        int k0 = s * 32;
        __syncthreads();
        #pragma unroll
        for (int it = 0; it < 4; it++) {
            int idx = tid + it * 256;
            int row = idx >> 3, c4 = (idx & 7) << 2;
            uint32_t off = (uint32_t)(row * 80 + c4 * 2);
            {   // A tile 128x32
                float4 v = *(const float4*)(A + (size_t)(m0 + row) * K + k0 + c4);
                uint32_t h01, h23, l01, l23; split4(v, h01, h23, l01, l23);
                *(uint2*)(smem + AH + off)  = make_uint2(h01, h23);
                *(uint2*)(smem + ALo + off) = make_uint2(l01, l23);
            }
            {   // B tile 128x32
                float4 v = *(const float4*)(W + (size_t)(n0 + row) * K + k0 + c4);
                uint32_t h01, h23, l01, l23; split4(v, h01, h23, l01, l23);
                *(uint2*)(smem + BH + off)  = make_uint2(h01, h23);
                *(uint2*)(smem + BLo + off) = make_uint2(l01, l23);
            }
        }
        __syncthreads();

        #pragma unroll
        for (int kk = 0; kk < 32; kk += 16) {
            // A fragments (4 m-tiles, hi+lo)
            uint32_t ah[4][4], al[4][4];
            #pragma unroll
            for (int i = 0; i < 4; i++) {
                int r = warp_m * 64 + i * 16 + g;
                uint32_t base = (uint32_t)(r * 80 + (kk + 2 * t) * 2);
                ah[i][0] = *(const uint32_t*)(smem + AH + base);
                ah[i][1] = *(const uint32_t*)(smem + AH + base + 8 * 80);
                ah[i][2] = *(const uint32_t*)(smem + AH + base + 16);
                ah[i][3] = *(const uint32_t*)(smem + AH + base + 8 * 80 + 16);
                al[i][0] = *(const uint32_t*)(smem + ALo + base);
                al[i][1] = *(const uint32_t*)(smem + ALo + base + 8 * 80);
                al[i][2] = *(const uint32_t*)(smem + ALo + base + 16);
                al[i][3] = *(const uint32_t*)(smem + ALo + base + 8 * 80 + 16);
            }
            #pragma unroll
            for (int j = 0; j < 4; j++) {
                int n = warp_n * 32 + j * 8 + g;
                uint32_t nb = (uint32_t)(n * 80 + (kk + 2 * t) * 2);
                uint32_t bh0 = *(const uint32_t*)(smem + BH + nb);
                uint32_t bh1 = *(const uint32_t*)(smem + BH + nb + 16);
                uint32_t bl0 = *(const uint32_t*)(smem + BLo + nb);
                uint32_t bl1 = *(const uint32_t*)(smem + BLo + nb + 16);
                #pragma unroll
                for (int i = 0; i < 4; i++) {
                    mma16816(acc[i][j], ah[i], bh0, bh1);
                    mma16816(acc[i][j], ah[i], bl0, bl1);
                    mma16816(acc[i][j], al[i], bh0, bh1);
                }
            }
        }
    }

    // epilogue
    #pragma unroll
    for (int i = 0; i < 4; i++) {
        #pragma unroll
        for (int j = 0; j < 4; j++) {
            int gm0 = m0 + warp_m * 64 + i * 16 + g;
            int gn  = n0 + warp_n * 32 + j * 8 + 2 * t;
            #pragma unroll
            for (int half = 0; half < 2; half++) {
                int gm = gm0 + half * 8;
                float v0 = acc[i][j][half * 2 + 0];
                float v1 = acc[i][j][half * 2 + 1];
                if (BIAS) { v0 += bias[gn]; v1 += bias[gn + 1]; }
                if (GELU) { v0 = gelu_exact(v0); v1 = gelu_exact(v1); }
                if (RES) {
                    float2 r2 = *(const float2*)(res + (size_t)gm * Nd + gn);
                    v0 += r2.x; v1 += r2.y;
                }
                *(float2*)(out + (size_t)gm * Nd + gn) = make_float2(v0, v1);
            }
        }
    }
#endif
}

// --------------------------- embed ------------------------------------------
__global__ void embed_kernel(const float* __restrict__ x,
                             const float* __restrict__ cls,
                             float* __restrict__ h)
{
    int row = blockIdx.x;
    int b = row / NN, n = row % NN;
    for (int c = threadIdx.x; c < CC; c += blockDim.x) {
        float base = (n == 0) ? cls[c]
                              : x[((size_t)b * (NN - 1) + (n - 1)) * CC + c];
        int jj = c & ~1;
        float div = __expf(-9.210340371976184f * (float)jj / 768.0f);
        float ang = (float)n * div;
        float pe  = (c & 1) ? cosf(ang) : sinf(ang);
        h[(size_t)row * CC + c] = base + pe;
    }
}

// --------------------------- layernorm ---------------------------------------
__global__ void ln_kernel(const float* __restrict__ x,
                          const float* __restrict__ w,
                          const float* __restrict__ bns,
                          float* __restrict__ y,
                          int in_row_stride)
{
    const float* xr = x + (size_t)blockIdx.x * in_row_stride * CC;
    float* yr = y + (size_t)blockIdx.x * CC;
    int t = threadIdx.x;
    float v0 = xr[t], v1 = xr[t + 256], v2 = xr[t + 512];
    float s = v0 + v1 + v2;
    float q = v0 * v0 + v1 * v1 + v2 * v2;
    #pragma unroll
    for (int o = 16; o; o >>= 1) {
        s += __shfl_xor_sync(0xffffffffu, s, o);
        q += __shfl_xor_sync(0xffffffffu, q, o);
    }
    __shared__ float ss[8], qs[8];
    if ((t & 31) == 0) { ss[t >> 5] = s; qs[t >> 5] = q; }
    __syncthreads();
    float tot = 0.f, totq = 0.f;
    #pragma unroll
    for (int i = 0; i < 8; i++) { tot += ss[i]; totq += qs[i]; }
    float mu   = tot * (1.0f / 768.0f);
    float var  = totq * (1.0f / 768.0f) - mu * mu;
    float rstd = rsqrtf(var + 1e-5f);
    yr[t]       = (v0 - mu) * rstd * w[t]       + bns[t];
    yr[t + 256] = (v1 - mu) * rstd * w[t + 256] + bns[t + 256];
    yr[t + 512] = (v2 - mu) * rstd * w[t + 512] + bns[t + 512];
}

// --------------------------- fused attention ---------------------------------
__global__ __launch_bounds__(256, 2)
void attn_kernel(const float* __restrict__ qkv, float* __restrict__ o)
{
    extern __shared__ float sm[];
    float* Ks = sm;
    float* Vs = sm + NN * DK;
    int bh = blockIdx.x;
    int b = bh / HH, h = bh % HH;
    const float* base = qkv + (size_t)b * NN * (3 * CC);

    for (int idx = threadIdx.x; idx < (NN * DK) / 4; idx += 256) {
        int row = idx >> 4, d4 = (idx & 15) << 2;
        const float* kp = base + (size_t)row * (3 * CC) +     CC + h * DK + d4;
        const float* vp = base + (size_t)row * (3 * CC) + 2 * CC + h * DK + d4;
        *(float4*)(Ks + row * DK + d4) = *(const float4*)kp;
        *(float4*)(Vs + row * DK + d4) = *(const float4*)vp;
    }
    __syncthreads();

    int grp = threadIdx.x >> 2, sub = threadIdx.x & 3;
    int i = blockIdx.y * 64 + grp;
    int ir = (i < NN) ? i : NN - 1;

    float q[16];
    const float* qp = base + (size_t)ir * (3 * CC) + h * DK + sub * 16;
    #pragma unroll
    for (int k = 0; k < 16; k += 4) {
        float4 v = *(const float4*)(qp + k);
        q[k] = v.x * 0.125f; q[k+1] = v.y * 0.125f;
        q[k+2] = v.z * 0.125f; q[k+3] = v.w * 0.125f;
    }

    float mx = -1e30f, l = 0.f;
    float acc[16];
    #pragma unroll
    for (int k = 0; k < 16; k++) acc[k] = 0.f;

    for (int j = 0; j < NN; j++) {
        const float* kr = Ks + j * DK + sub * 16;
        float s = 0.f;
        #pragma unroll
        for (int k = 0; k < 16; k += 4) {
            float4 v = *(const float4*)(kr + k);
            s += q[k] * v.x + q[k+1] * v.y + q[k+2] * v.z + q[k+3] * v.w;
        }
        s += __shfl_xor_sync(0xffffffffu, s, 1);
        s += __shfl_xor_sync(0xffffffffu, s, 2);
        if (s > mx) {
            float cr = __expf(mx - s);
            l *= cr;
            #pragma unroll
            for (int k = 0; k < 16; k++) acc[k] *= cr;
            mx = s;
        }
        float p = __expf(s - mx);
        l += p;
        const float* vr = Vs + j * DK + sub * 16;
        #pragma unroll
        for (int k = 0; k < 16; k += 4) {
            float4 v = *(const float4*)(vr + k);
            acc[k]   += p * v.x; acc[k+1] += p * v.y;
            acc[k+2] += p * v.z; acc[k+3] += p * v.w;
        }
    }

    if (i < NN) {
        float inv = 1.0f / l;
        float* op = o + (size_t)(b * NN + i) * CC + h * DK + sub * 16;
        #pragma unroll
        for (int k = 0; k < 16; k += 4) {
            *(float4*)(op + k) = make_float4(acc[k]*inv, acc[k+1]*inv,
                                             acc[k+2]*inv, acc[k+3]*inv);
        }
    }
}

// --------------------------- small SIMT GEMM (head) --------------------------
template<bool BIAS>
__global__ void gemm_nt(const float* __restrict__ A, const float* __restrict__ W,
                        const float* __restrict__ bias, float* __restrict__ out,
                        int M, int Nd, int K)
{
    const int BM = 128, BN = 128, BK = 8;
    __shared__ float As[BK][BM + 4];
    __shared__ float Ws[BK][BN + 4];
    int t = threadIdx.x, tx = t & 15, ty = t >> 4;
    int m0 = blockIdx.x * BM, n0 = blockIdx.y * BN;
    int lrow = t >> 1, lk = (t & 1) * 4;
    float acc[8][8];
    #pragma unroll
    for (int i = 0; i < 8; i++)
        #pragma unroll
        for (int j = 0; j < 8; j++) acc[i][j] = 0.f;
    for (int k0 = 0; k0 < K; k0 += BK) {
        int gm = m0 + lrow;
        float4 va = (gm < M) ? *(const float4*)(A + (size_t)gm * K + k0 + lk)
                             : make_float4(0,0,0,0);
        As[lk+0][lrow]=va.x; As[lk+1][lrow]=va.y; As[lk+2][lrow]=va.z; As[lk+3][lrow]=va.w;
        int gn = n0 + lrow;
        float4 vw = (gn < Nd) ? *(const float4*)(W + (size_t)gn * K + k0 + lk)
                              : make_float4(0,0,0,0);
        Ws[lk+0][lrow]=vw.x; Ws[lk+1][lrow]=vw.y; Ws[lk+2][lrow]=vw.z; Ws[lk+3][lrow]=vw.w;
        __syncthreads();
        #pragma unroll
        for (int k = 0; k < BK; k++) {
            float ra[8], rb[8];
            *(float4*)(ra)   = *(const float4*)&As[k][ty*8];
            *(float4*)(ra+4) = *(const float4*)&As[k][ty*8+4];
            *(float4*)(rb)   = *(const float4*)&Ws[k][tx*8];
            *(float4*)(rb+4) = *(const float4*)&Ws[k][tx*8+4];
            #pragma unroll
            for (int i = 0; i < 8; i++)
                #pragma unroll
                for (int j = 0; j < 8; j++) acc[i][j] += ra[i] * rb[j];
        }
        __syncthreads();
    }
    #pragma unroll
    for (int i = 0; i < 8; i++) {
        int gm = m0 + ty * 8 + i;
        if (gm >= M) continue;
        #pragma unroll
        for (int j = 0; j < 8; j++) {
            int gn = n0 + tx * 8 + j;
            if (gn >= Nd) continue;
            float v = acc[i][j];
            if (BIAS) v += bias[gn];
            out[(size_t)gm * Nd + gn] = v;
        }
    }
}

// ---------------------------------------------------------------------------
extern "C" void kernel_launch(void* const* d_in, const int* in_sizes, int n_in,
                              void* d_out, int out_size)
{
    const float* x      = (const float*)d_in[0];
    const float* cls    = (const float*)d_in[1];
    const float* qkv_w  = (const float*)d_in[2];
    const float* proj_w = (const float*)d_in[3];
    const float* proj_b = (const float*)d_in[4];
    const float* ln1_w  = (const float*)d_in[5];
    const float* ln1_b  = (const float*)d_in[6];
    const float* ln2_w  = (const float*)d_in[7];
    const float* ln2_b  = (const float*)d_in[8];
    const float* fc1_w  = (const float*)d_in[9];
    const float* fc1_b  = (const float*)d_in[10];
    const float* fc2_w  = (const float*)d_in[11];
    const float* fc2_b  = (const float*)d_in[12];
    const float* norm_w = (const float*)d_in[13];
    const float* norm_b = (const float*)d_in[14];
    const float* head_w = (const float*)d_in[15];
    const float* head_b = (const float*)d_in[16];
    float* out = (float*)d_out;

    float *ph, *py, *pqkv, *po, *pm, *pcls;
    cudaGetSymbolAddress((void**)&ph,   g_h);
    cudaGetSymbolAddress((void**)&py,   g_y);
    cudaGetSymbolAddress((void**)&pqkv, g_qkv);
    cudaGetSymbolAddress((void**)&po,   g_o);
    cudaGetSymbolAddress((void**)&pm,   g_m);
    cudaGetSymbolAddress((void**)&pcls, g_cls);

    const int attn_smem = NN * DK * 2 * (int)sizeof(float);
    cudaFuncSetAttribute(attn_kernel,
                         cudaFuncAttributeMaxDynamicSharedMemorySize, attn_smem);
    cudaFuncSetAttribute(gemm_tc<false,false,false>,
                         cudaFuncAttributeMaxDynamicSharedMemorySize, GT_SMEM);
    cudaFuncSetAttribute(gemm_tc<true,false,true>,
                         cudaFuncAttributeMaxDynamicSharedMemorySize, GT_SMEM);
    cudaFuncSetAttribute(gemm_tc<true,true,false>,
                         cudaFuncAttributeMaxDynamicSharedMemorySize, GT_SMEM);

    embed_kernel<<<TT, 256>>>(x, cls, ph);

    const int MTT = MP / 128;  // 99

    for (int d = 0; d < NL; d++) {
        const float* qw  = qkv_w  + (size_t)d * 3 * CC * CC;
        const float* pw  = proj_w + (size_t)d * CC * CC;
        const float* pb  = proj_b + (size_t)d * CC;
        const float* l1w = ln1_w  + (size_t)d * CC;
        const float* l1b = ln1_b  + (size_t)d * CC;
        const float* l2w = ln2_w  + (size_t)d * CC;
        const float* l2b = ln2_b  + (size_t)d * CC;
        const float* f1w = fc1_w  + (size_t)d * FF * CC;
        const float* f1b = fc1_b  + (size_t)d * FF;
        const float* f2w = fc2_w  + (size_t)d * CC * FF;
        const float* f2b = fc2_b  + (size_t)d * CC;

        ln_kernel<<<TT, 256>>>(ph, l1w, l1b, py, 1);
        gemm_tc<false,false,false><<<dim3(MTT, (3*CC)/128), 256, GT_SMEM>>>(
            py, qw, nullptr, nullptr, pqkv, MP, 3*CC, CC);
        attn_kernel<<<dim3(BB*HH, 4), 256, attn_smem>>>(pqkv, po);
        gemm_tc<true,false,true><<<dim3(MTT, CC/128), 256, GT_SMEM>>>(
            po, pw, pb, ph, ph, MP, CC, CC);
        ln_kernel<<<TT, 256>>>(ph, l2w, l2b, py, 1);
        gemm_tc<true,true,false><<<dim3(MTT, FF/128), 256, GT_SMEM>>>(
            py, f1w, f1b, nullptr, pm, MP, FF, CC);
        gemm_tc<true,false,true><<<dim3(MTT, CC/128), 256, GT_SMEM>>>(
            pm, f2w, f2b, ph, ph, MP, CC, FF);
    }

    ln_kernel<<<BB, 256>>>(ph, norm_w, norm_b, pcls, NN);
    gemm_nt<true><<<dim3(1, (VV + 127) / 128), 256>>>(
        pcls, head_w, head_b, out, BB, VV, CC);
}